// round 1
// baseline (speedup 1.0000x reference)
#include <cuda_runtime.h>

#define NCOEF 25
#define ROWS_PER_BLOCK 256
#define THREADS 256
// floats per block staged in smem
#define BLK_FLOATS (ROWS_PER_BLOCK * NCOEF)      // 6400
#define BLK_FLOAT4 (BLK_FLOATS / 4)              // 1600

__global__ __launch_bounds__(THREADS)
void parcor_to_lpc_kernel(const float* __restrict__ in,
                          float* __restrict__ out,
                          int nrows)
{
    __shared__ float s[BLK_FLOATS];

    const int tid = threadIdx.x;
    const long long block_row0 = (long long)blockIdx.x * ROWS_PER_BLOCK;

    const bool full_block = (block_row0 + ROWS_PER_BLOCK) <= (long long)nrows;

    if (full_block) {
        // ---- Phase 1: coalesced float4 load of 256 rows into smem ----
        const float4* __restrict__ gin =
            reinterpret_cast<const float4*>(in + block_row0 * NCOEF);
        float4* s4 = reinterpret_cast<float4*>(s);
        #pragma unroll
        for (int i = 0; i < 7; ++i) {
            int idx = tid + i * THREADS;
            if (idx < BLK_FLOAT4) s4[idx] = gin[idx];
        }
    } else {
        // tail fallback: scalar guarded loads
        for (int idx = tid; idx < BLK_FLOATS; idx += THREADS) {
            long long r = block_row0 + idx / NCOEF;
            s[idx] = (r < nrows) ? in[r * NCOEF + (idx % NCOEF)] : 0.0f;
        }
    }
    __syncthreads();

    // ---- Phase 2: per-thread in-register Levinson step-up ----
    float a[NCOEF];
    #pragma unroll
    for (int j = 0; j < NCOEF; ++j) a[j] = s[tid * NCOEF + j];

    #pragma unroll
    for (int m = 2; m <= NCOEF - 1; ++m) {
        const float km = a[m];          // a[m] == k[m], never overwritten
        int i = 1, j = m - 1;
        #pragma unroll
        for (; i < j; ++i, --j) {
            float ai = a[i], aj = a[j];
            a[i] = fmaf(km, aj, ai);
            a[j] = fmaf(km, ai, aj);
        }
        if (i == j) {
            float ai = a[i];
            a[i] = fmaf(km, ai, ai);
        }
    }

    #pragma unroll
    for (int j = 0; j < NCOEF; ++j) s[tid * NCOEF + j] = a[j];
    __syncthreads();

    // ---- Phase 3: coalesced float4 store ----
    if (full_block) {
        float4* __restrict__ gout =
            reinterpret_cast<float4*>(out + block_row0 * NCOEF);
        const float4* s4 = reinterpret_cast<const float4*>(s);
        #pragma unroll
        for (int i = 0; i < 7; ++i) {
            int idx = tid + i * THREADS;
            if (idx < BLK_FLOAT4) gout[idx] = s4[idx];
        }
    } else {
        for (int idx = tid; idx < BLK_FLOATS; idx += THREADS) {
            long long r = block_row0 + idx / NCOEF;
            if (r < nrows) out[r * NCOEF + (idx % NCOEF)] = s[idx];
        }
    }
}

extern "C" void kernel_launch(void* const* d_in, const int* in_sizes, int n_in,
                              void* d_out, int out_size)
{
    const float* k = (const float*)d_in[0];
    float* out = (float*)d_out;
    int nrows = in_sizes[0] / NCOEF;   // 2097152 for the bench shape
    int blocks = (nrows + ROWS_PER_BLOCK - 1) / ROWS_PER_BLOCK;
    parcor_to_lpc_kernel<<<blocks, THREADS>>>(k, out, nrows);
}